// round 4
// baseline (speedup 1.0000x reference)
#include <cuda_runtime.h>

#define HWN (512 * 1024)   // 2^19 pixels per batch image
#define NN  (8 * HWN)
#define SAME_RANGE 0.2f

// Scratch (allocation-free):
// g_acc[t]  = (sum_c0, sum_c1, sum_c2, count), accumulated with one v4 RED.
// g_dlut[t] = min depth bits (depth in [0,1): uint order == float order).
__device__ float4 g_acc[NN];          // 64MB
__device__ unsigned int g_dlut[NN];   // 16MB

// Scalar target index for source pixel i (matches reference: clip, then
// round-half-even).
__device__ __forceinline__ int target_index(int i, const float* __restrict__ flow) {
    int b = i >> 19;             // HWN = 2^19
    int p = i & (HWN - 1);
    int y = p >> 10;             // W = 1024
    int x = p & 1023;
    const float* fb = flow + (size_t)b * 2 * HWN;
    float px = fminf(fmaxf((float)x + fb[p], 0.0f), 1023.0f);
    float py = fminf(fmaxf((float)y + fb[HWN + p], 0.0f), 511.0f);
    return (b << 19) + ((int)rintf(py) << 10) + (int)rintf(px);
}

// Pass 1: z-buffer min. Scalar (1 px/thread) for maximum warp-level latency
// hiding of the scattered RED.MIN traffic.
__global__ void zmin_kernel(const float* __restrict__ flow,
                            const float* __restrict__ depth) {
    int i = blockIdx.x * blockDim.x + threadIdx.x;
    int t = target_index(i, flow);
    atomicMin(&g_dlut[t], __float_as_uint(depth[i]));
}

__device__ __forceinline__ void red_add_v4(float4* p, float a, float b, float c, float d) {
    asm volatile("red.global.add.v4.f32 [%0], {%1, %2, %3, %4};"
                 :: "l"(p), "f"(a), "f"(b), "f"(c), "f"(d) : "memory");
}

// Pass 2: keep-test against z-buffer, splat (c0, c1, c2, 1) with a single
// 16B vector RED per kept source pixel. Scalar for TLP.
__global__ void splat_kernel(const float* __restrict__ obj,
                             const float* __restrict__ flow,
                             const float* __restrict__ depth) {
    int i = blockIdx.x * blockDim.x + threadIdx.x;
    int t = target_index(i, flow);
    float d = depth[i];
    float dmin = __uint_as_float(g_dlut[t]);
    if (d <= dmin + SAME_RANGE) {
        int b = i >> 19;
        int p = i & (HWN - 1);
        const float* ob = obj + (size_t)b * 3 * HWN;
        float c0 = ob[0 * HWN + p];
        float c1 = ob[1 * HWN + p];
        float c2 = ob[2 * HWN + p];
        red_add_v4(&g_acc[t], c0, c1, c2, 1.0f);
    }
}

// Pass 3: out = sum / count (0 where count == 0). Vectorized streaming;
// writes every output pixel so no out memset is needed.
__global__ void normalize_kernel(float* __restrict__ out) {
    int i = (blockIdx.x * blockDim.x + threadIdx.x) << 2;
    int b = i >> 19;
    int p = i & (HWN - 1);

    float4 a0 = g_acc[i + 0];
    float4 a1 = g_acc[i + 1];
    float4 a2 = g_acc[i + 2];
    float4 a3 = g_acc[i + 3];

    float r0 = a0.w > 0.0f ? __fdividef(1.0f, a0.w) : 0.0f;
    float r1 = a1.w > 0.0f ? __fdividef(1.0f, a1.w) : 0.0f;
    float r2 = a2.w > 0.0f ? __fdividef(1.0f, a2.w) : 0.0f;
    float r3 = a3.w > 0.0f ? __fdividef(1.0f, a3.w) : 0.0f;

    float4 c0 = make_float4(a0.x * r0, a1.x * r1, a2.x * r2, a3.x * r3);
    float4 c1 = make_float4(a0.y * r0, a1.y * r1, a2.y * r2, a3.y * r3);
    float4 c2 = make_float4(a0.z * r0, a1.z * r1, a2.z * r2, a3.z * r3);

    float* outb = out + (size_t)b * 3 * HWN;
    *reinterpret_cast<float4*>(outb + 0 * HWN + p) = c0;
    *reinterpret_cast<float4*>(outb + 1 * HWN + p) = c1;
    *reinterpret_cast<float4*>(outb + 2 * HWN + p) = c2;
}

extern "C" void kernel_launch(void* const* d_in, const int* in_sizes, int n_in,
                              void* d_out, int out_size) {
    const float* obj   = (const float*)d_in[0];
    const float* flow  = (const float*)d_in[1];
    const float* depth = (const float*)d_in[2];
    float* out = (float*)d_out;

    void* acc_ptr = nullptr;
    void* dlut_ptr = nullptr;
    cudaGetSymbolAddress(&acc_ptr, g_acc);
    cudaGetSymbolAddress(&dlut_ptr, g_dlut);

    // dlut -> 0xFFFFFFFF (atomicMin identity; real depth bits < 0x3F800000).
    // acc  -> 0 (sums + counts).
    cudaMemsetAsync(dlut_ptr, 0xFF, (size_t)NN * sizeof(unsigned int), 0);
    cudaMemsetAsync(acc_ptr, 0, (size_t)NN * sizeof(float4), 0);

    const int TPB = 256;
    const int blocks_scalar = NN / TPB;       // exact: NN = 4M
    const int blocks_vec4   = NN / 4 / TPB;
    zmin_kernel<<<blocks_scalar, TPB, 0, 0>>>(flow, depth);
    splat_kernel<<<blocks_scalar, TPB, 0, 0>>>(obj, flow, depth);
    normalize_kernel<<<blocks_vec4, TPB, 0, 0>>>(out);
}

// round 7
// speedup vs baseline: 1.2813x; 1.2813x over previous
#include <cuda_runtime.h>

#define HWN (512 * 1024)   // 2^19 pixels per batch image
#define NN  (8 * HWN)
#define SAME_RANGE 0.2f

// Scratch (allocation-free):
// g_acc[t]  = (sum_c0, sum_c1, sum_c2, count), accumulated with one v4 RED.
// g_dlut[t] = min depth bits (depth in [0,1): uint order == float order).
// Together 80MB — kept L2-resident (126MB) by using evict-first (.cs) policy
// on all streaming traffic.
__device__ float4 g_acc[NN];          // 64MB
__device__ unsigned int g_dlut[NN];   // 16MB

__device__ __forceinline__ void targets4(int i, const float* __restrict__ flow,
                                         int4& t) {
    int b = i >> 19;              // HWN = 2^19
    int p = i & (HWN - 1);
    int y = p >> 10;              // W = 1024
    int x = p & 1023;
    const float* fb = flow + (size_t)b * 2 * HWN;
    float4 fx = __ldcs(reinterpret_cast<const float4*>(fb + p));
    float4 fy = __ldcs(reinterpret_cast<const float4*>(fb + HWN + p));
    float yf = (float)y;

    float px0 = fminf(fmaxf((float)(x + 0) + fx.x, 0.0f), 1023.0f);
    float px1 = fminf(fmaxf((float)(x + 1) + fx.y, 0.0f), 1023.0f);
    float px2 = fminf(fmaxf((float)(x + 2) + fx.z, 0.0f), 1023.0f);
    float px3 = fminf(fmaxf((float)(x + 3) + fx.w, 0.0f), 1023.0f);
    float py0 = fminf(fmaxf(yf + fy.x, 0.0f), 511.0f);
    float py1 = fminf(fmaxf(yf + fy.y, 0.0f), 511.0f);
    float py2 = fminf(fmaxf(yf + fy.z, 0.0f), 511.0f);
    float py3 = fminf(fmaxf(yf + fy.w, 0.0f), 511.0f);

    int base = b << 19;
    t.x = base + ((int)rintf(py0) << 10) + (int)rintf(px0);
    t.y = base + ((int)rintf(py1) << 10) + (int)rintf(px1);
    t.z = base + ((int)rintf(py2) << 10) + (int)rintf(px2);
    t.w = base + ((int)rintf(py3) << 10) + (int)rintf(px3);
}

// Pass 1: z-buffer min over depth bits.
__global__ void zmin_kernel(const float* __restrict__ flow,
                            const float* __restrict__ depth) {
    int i = (blockIdx.x * blockDim.x + threadIdx.x) << 2;
    int4 t;
    targets4(i, flow, t);
    float4 d = __ldcs(reinterpret_cast<const float4*>(depth + i));
    atomicMin(&g_dlut[t.x], __float_as_uint(d.x));
    atomicMin(&g_dlut[t.y], __float_as_uint(d.y));
    atomicMin(&g_dlut[t.z], __float_as_uint(d.z));
    atomicMin(&g_dlut[t.w], __float_as_uint(d.w));
}

__device__ __forceinline__ void red_add_v4(float4* p, float a, float b, float c, float d) {
    asm volatile("red.global.add.v4.f32 [%0], {%1, %2, %3, %4};"
                 :: "l"(p), "f"(a), "f"(b), "f"(c), "f"(d) : "memory");
}

// Pass 2: keep-test against z-buffer, one 16B vector RED per kept pixel.
__global__ void splat_kernel(const float* __restrict__ obj,
                             const float* __restrict__ flow,
                             const float* __restrict__ depth) {
    int i = (blockIdx.x * blockDim.x + threadIdx.x) << 2;
    int4 t;
    targets4(i, flow, t);
    float4 d = __ldcs(reinterpret_cast<const float4*>(depth + i));

    float m0 = __uint_as_float(g_dlut[t.x]) + SAME_RANGE;
    float m1 = __uint_as_float(g_dlut[t.y]) + SAME_RANGE;
    float m2 = __uint_as_float(g_dlut[t.z]) + SAME_RANGE;
    float m3 = __uint_as_float(g_dlut[t.w]) + SAME_RANGE;

    int b = i >> 19;
    int p = i & (HWN - 1);
    const float* ob = obj + (size_t)b * 3 * HWN;
    float4 o0 = __ldcs(reinterpret_cast<const float4*>(ob + 0 * HWN + p));
    float4 o1 = __ldcs(reinterpret_cast<const float4*>(ob + 1 * HWN + p));
    float4 o2 = __ldcs(reinterpret_cast<const float4*>(ob + 2 * HWN + p));

    if (d.x <= m0) red_add_v4(&g_acc[t.x], o0.x, o1.x, o2.x, 1.0f);
    if (d.y <= m1) red_add_v4(&g_acc[t.y], o0.y, o1.y, o2.y, 1.0f);
    if (d.z <= m2) red_add_v4(&g_acc[t.z], o0.z, o1.z, o2.z, 1.0f);
    if (d.w <= m3) red_add_v4(&g_acc[t.w], o0.w, o1.w, o2.w, 1.0f);
}

// Pass 3: out = sum / count (0 where count == 0). acc reads should hit L2;
// output stores use evict-first so they don't disturb anything.
__global__ void normalize_kernel(float* __restrict__ out) {
    int i = (blockIdx.x * blockDim.x + threadIdx.x) << 2;
    int b = i >> 19;
    int p = i & (HWN - 1);

    float4 a0 = __ldcs(&g_acc[i + 0]);
    float4 a1 = __ldcs(&g_acc[i + 1]);
    float4 a2 = __ldcs(&g_acc[i + 2]);
    float4 a3 = __ldcs(&g_acc[i + 3]);

    float r0 = a0.w > 0.0f ? __fdividef(1.0f, a0.w) : 0.0f;
    float r1 = a1.w > 0.0f ? __fdividef(1.0f, a1.w) : 0.0f;
    float r2 = a2.w > 0.0f ? __fdividef(1.0f, a2.w) : 0.0f;
    float r3 = a3.w > 0.0f ? __fdividef(1.0f, a3.w) : 0.0f;

    float4 c0 = make_float4(a0.x * r0, a1.x * r1, a2.x * r2, a3.x * r3);
    float4 c1 = make_float4(a0.y * r0, a1.y * r1, a2.y * r2, a3.y * r3);
    float4 c2 = make_float4(a0.z * r0, a1.z * r1, a2.z * r2, a3.z * r3);

    float* outb = out + (size_t)b * 3 * HWN;
    __stcs(reinterpret_cast<float4*>(outb + 0 * HWN + p), c0);
    __stcs(reinterpret_cast<float4*>(outb + 1 * HWN + p), c1);
    __stcs(reinterpret_cast<float4*>(outb + 2 * HWN + p), c2);
}

extern "C" void kernel_launch(void* const* d_in, const int* in_sizes, int n_in,
                              void* d_out, int out_size) {
    const float* obj   = (const float*)d_in[0];
    const float* flow  = (const float*)d_in[1];
    const float* depth = (const float*)d_in[2];
    float* out = (float*)d_out;

    void* acc_ptr = nullptr;
    void* dlut_ptr = nullptr;
    cudaGetSymbolAddress(&acc_ptr, g_acc);
    cudaGetSymbolAddress(&dlut_ptr, g_dlut);

    const int TPB = 256;
    const int blocks = NN / 4 / TPB;  // exact: NN = 4M

    // dlut -> 0xFFFFFFFF (atomicMin identity; real depth bits < 0x3F800000).
    cudaMemsetAsync(dlut_ptr, 0xFF, (size_t)NN * sizeof(unsigned int), 0);
    zmin_kernel<<<blocks, TPB, 0, 0>>>(flow, depth);

    // Clear acc immediately before splat so the zeroed lines are still
    // L2-resident when the REDs hit them (no DRAM read-allocate).
    cudaMemsetAsync(acc_ptr, 0, (size_t)NN * sizeof(float4), 0);
    splat_kernel<<<blocks, TPB, 0, 0>>>(obj, flow, depth);

    normalize_kernel<<<blocks, TPB, 0, 0>>>(out);
}